// round 8
// baseline (speedup 1.0000x reference)
#include <cuda_runtime.h>

#define BB 8
#define LL 1024
#define DD 768
#define NH 12
#define DH 64

// ---------------- scratch (no cudaMalloc allowed) ----------------
__device__ float g_Qp[BB * LL * DD];   // projected Q  [B*L, 768]
__device__ float g_Kp[BB * LL * DD];   // projected K  [B*L, 768]
__device__ float g_Attn[BB * LL * LL]; // fallback attn scratch
__device__ float g_Out[BB * LL * DD];  // fallback out scratch

// =================================================================
// Projection GEMM:  C[m,n] = sum_k A[m,k] * W[n,k] + bias[n]
// A [8192,768] row-major, W [768,768] row-major ([out,in] torch layout)
// 128x128 block tile, BK=8, 256 threads, 8x8 microtile (split 4+64)
// =================================================================
__global__ __launch_bounds__(256, 2)
void proj_kernel(const float* __restrict__ A, const float* __restrict__ W,
                 const float* __restrict__ bias, int which)
{
    float* C = which ? g_Kp : g_Qp;
    __shared__ float As[8][128];
    __shared__ float Ws[8][128];

    const int tid = threadIdx.x;
    const int tx = tid & 15;
    const int ty = tid >> 4;
    const int m0 = blockIdx.y * 128;
    const int n0 = blockIdx.x * 128;

    const int lrow = tid >> 1;        // 0..127
    const int lcol = (tid & 1) * 4;   // 0 or 4

    float acc[8][8];
#pragma unroll
    for (int i = 0; i < 8; i++)
#pragma unroll
        for (int j = 0; j < 8; j++) acc[i][j] = 0.f;

    const float* Ag = A + (size_t)(m0 + lrow) * DD + lcol;
    const float* Wg = W + (size_t)(n0 + lrow) * DD + lcol;

    for (int k0 = 0; k0 < DD; k0 += 8) {
        float4 av = *(const float4*)(Ag + k0);
        float4 wv = *(const float4*)(Wg + k0);
        __syncthreads();
        As[lcol + 0][lrow] = av.x; As[lcol + 1][lrow] = av.y;
        As[lcol + 2][lrow] = av.z; As[lcol + 3][lrow] = av.w;
        Ws[lcol + 0][lrow] = wv.x; Ws[lcol + 1][lrow] = wv.y;
        Ws[lcol + 2][lrow] = wv.z; Ws[lcol + 3][lrow] = wv.w;
        __syncthreads();
#pragma unroll
        for (int k = 0; k < 8; k++) {
            float a[8], b[8];
            *(float4*)&a[0] = *(const float4*)&As[k][ty * 4];
            *(float4*)&a[4] = *(const float4*)&As[k][ty * 4 + 64];
            *(float4*)&b[0] = *(const float4*)&Ws[k][tx * 4];
            *(float4*)&b[4] = *(const float4*)&Ws[k][tx * 4 + 64];
#pragma unroll
            for (int i = 0; i < 8; i++)
#pragma unroll
                for (int j = 0; j < 8; j++) acc[i][j] += a[i] * b[j];
        }
    }

    float4 bv[2];
    bv[0] = *(const float4*)&bias[n0 + tx * 4];
    bv[1] = *(const float4*)&bias[n0 + tx * 4 + 64];

#pragma unroll
    for (int ih = 0; ih < 2; ih++)
#pragma unroll
        for (int i = 0; i < 4; i++) {
            int m = m0 + ty * 4 + i + ih * 64;
#pragma unroll
            for (int jh = 0; jh < 2; jh++) {
                float4 o;
                o.x = acc[ih * 4 + i][jh * 4 + 0] + bv[jh].x;
                o.y = acc[ih * 4 + i][jh * 4 + 1] + bv[jh].y;
                o.z = acc[ih * 4 + i][jh * 4 + 2] + bv[jh].z;
                o.w = acc[ih * 4 + i][jh * 4 + 3] + bv[jh].w;
                *(float4*)&C[(size_t)m * DD + n0 + tx * 4 + jh * 64] = o;
            }
        }
}

// =================================================================
// Zero the attn accumulator
// =================================================================
__global__ void zero_attn_kernel(float* p)
{
    float* a = p ? p : g_Attn;
    size_t i = (size_t)blockIdx.x * blockDim.x + threadIdx.x;
    a[i] = 0.f;
}

// =================================================================
// warp helpers
// =================================================================
__device__ __forceinline__ float warp_sum(float v)
{
#pragma unroll
    for (int o = 16; o > 0; o >>= 1) v += __shfl_xor_sync(0xffffffffu, v, o);
    return v;
}
__device__ __forceinline__ float warp_max(float v)
{
#pragma unroll
    for (int o = 16; o > 0; o >>= 1) v = fmaxf(v, __shfl_xor_sync(0xffffffffu, v, o));
    return v;
}

// =================================================================
// Attention kernel: per block (b, h, 16 q-rows)
//   scores[16][1024] register-resident (warp owns rows qy, qy+8;
//   lane owns 32 keys of each row), sparsemax per row via bisection,
//   nonzeros atomically accumulated into attn_mean (scaled 1/12).
// =================================================================
__global__ __launch_bounds__(256, 2)
void attn_kernel(float* __restrict__ attn_arg)
{
    float* attn = attn_arg ? attn_arg : g_Attn;

    __shared__ float Qs[16][64];
    __shared__ float Ks[128][65];

    const int tid  = threadIdx.x;
    const int lane = tid & 31;
    const int warp = tid >> 5;        // 0..7 -> q rows (warp, warp+8)
    const int qt = blockIdx.x;        // 0..63
    const int h  = blockIdx.y;        // 0..11
    const int b  = blockIdx.z;        // 0..7

    const float* Qp = g_Qp + ((size_t)b * LL + qt * 16) * DD + h * DH;
    const float* Kp = g_Kp + (size_t)b * LL * DD + h * DH;

    // load Q tile: 16 rows x 64 dims (exactly 256 float4s)
    {
        int r = tid >> 4;
        int c = (tid & 15) * 4;
        *(float4*)&Qs[r][c] = *(const float4*)(Qp + (size_t)r * DD + c);
    }

    float s0[32], s1[32];
    const int qy = warp;

#pragma unroll
    for (int kt = 0; kt < 8; kt++) {
        __syncthreads();
        // load 128 keys x 64 dims
#pragma unroll
        for (int it = 0; it < 8; it++) {
            int r = (tid >> 4) + it * 16;
            int c = (tid & 15) * 4;
            float4 vv = *(const float4*)(Kp + (size_t)(kt * 128 + r) * DD + c);
            Ks[r][c + 0] = vv.x; Ks[r][c + 1] = vv.y;
            Ks[r][c + 2] = vv.z; Ks[r][c + 3] = vv.w;
        }
        __syncthreads();

        float a0 = 0.f, a1 = 0.f, a2 = 0.f, a3 = 0.f;
        float c0 = 0.f, c1 = 0.f, c2 = 0.f, c3 = 0.f;
#pragma unroll 8
        for (int d = 0; d < 64; d++) {
            float q0 = Qs[qy][d];
            float q1 = Qs[qy + 8][d];
            float k0 = Ks[lane][d];
            float k1 = Ks[lane + 32][d];
            float k2 = Ks[lane + 64][d];
            float k3 = Ks[lane + 96][d];
            a0 += q0 * k0; a1 += q0 * k1; a2 += q0 * k2; a3 += q0 * k3;
            c0 += q1 * k0; c1 += q1 * k1; c2 += q1 * k2; c3 += q1 * k3;
        }
        s0[kt * 4 + 0] = a0; s0[kt * 4 + 1] = a1;
        s0[kt * 4 + 2] = a2; s0[kt * 4 + 3] = a3;
        s1[kt * 4 + 0] = c0; s1[kt * 4 + 1] = c1;
        s1[kt * 4 + 2] = c2; s1[kt * 4 + 3] = c3;
    }

    // scale by 1/sqrt(64)
#pragma unroll
    for (int r = 0; r < 32; r++) { s0[r] *= 0.125f; s1[r] *= 0.125f; }

    // ---- sparsemax per row via bisection on tau ----
    float m0 = s0[0], m1 = s1[0];
#pragma unroll
    for (int r = 1; r < 32; r++) { m0 = fmaxf(m0, s0[r]); m1 = fmaxf(m1, s1[r]); }
    m0 = warp_max(m0);
    m1 = warp_max(m1);

    // f(tau) = sum max(z - tau, 0) - 1 ; f(max-1) >= 0 >= -1 = f(max)-...
    float lo0 = m0 - 1.f, hi0 = m0;
    float lo1 = m1 - 1.f, hi1 = m1;
    for (int it = 0; it < 26; it++) {
        float t0 = 0.5f * (lo0 + hi0);
        float t1 = 0.5f * (lo1 + hi1);
        float f0 = 0.f, f1 = 0.f;
#pragma unroll
        for (int r = 0; r < 32; r++) {
            f0 += fmaxf(s0[r] - t0, 0.f);
            f1 += fmaxf(s1[r] - t1, 0.f);
        }
        f0 = warp_sum(f0);
        f1 = warp_sum(f1);
        if (f0 >= 1.f) lo0 = t0; else hi0 = t0;   // uniform across warp
        if (f1 >= 1.f) lo1 = t1; else hi1 = t1;
    }
    // exact threshold from localized support
    float t0 = 0.5f * (lo0 + hi0);
    float t1 = 0.5f * (lo1 + hi1);
    float k0 = 0.f, S0 = 0.f, k1 = 0.f, S1 = 0.f;
#pragma unroll
    for (int r = 0; r < 32; r++) {
        if (s0[r] > t0) { k0 += 1.f; S0 += s0[r]; }
        if (s1[r] > t1) { k1 += 1.f; S1 += s1[r]; }
    }
    k0 = warp_sum(k0); S0 = warp_sum(S0);
    k1 = warp_sum(k1); S1 = warp_sum(S1);
    float tau0 = (S0 - 1.f) / k0;
    float tau1 = (S1 - 1.f) / k1;

    // ---- scatter nonzeros into head-mean attn ----
    const float inv12 = 1.f / 12.f;
    const int q0row = qt * 16 + warp;
    float* arow0 = attn + ((size_t)b * LL + q0row) * LL;
    float* arow1 = arow0 + (size_t)8 * LL;
#pragma unroll
    for (int r = 0; r < 32; r++) {
        int j = (r >> 2) * 128 + (r & 3) * 32 + lane;
        float a = s0[r] - tau0;
        if (a > 0.f) atomicAdd(&arow0[j], a * inv12);
        float c = s1[r] - tau1;
        if (c > 0.f) atomicAdd(&arow1[j], c * inv12);
    }
}

// =================================================================
// Output kernel: out[b,q,:] = sum_j attn[b,q,j] * v[b,j,:]
// Sparse gather: compact nonzeros (deterministic order), then gather
// v rows (L2-resident). 192 threads, each owns 4 output dims (float4).
// =================================================================
__global__ __launch_bounds__(192)
void out_kernel(const float* __restrict__ attn_arg, const float* __restrict__ v,
                float* __restrict__ out_arg)
{
    const float* attn = attn_arg ? attn_arg : g_Attn;
    float* out = out_arg ? out_arg : g_Out;

    __shared__ float srow[1024];
    __shared__ float svals[1024];
    __shared__ unsigned short sidx[1024];
    __shared__ int scnt;

    const int tid = threadIdx.x;
    const int q = blockIdx.x;
    const int b = blockIdx.y;

    const float* arow = attn + ((size_t)b * LL + q) * LL;
    for (int i = tid; i < 1024; i += 192) srow[i] = arow[i];
    __syncthreads();

    if (tid < 32) {
        int total = 0;
        for (int base = 0; base < 1024; base += 32) {
            float val = srow[base + tid];
            unsigned mask = __ballot_sync(0xffffffffu, val != 0.f);
            if (val != 0.f) {
                int pos = total + __popc(mask & ((1u << tid) - 1u));
                svals[pos] = val;
                sidx[pos] = (unsigned short)(base + tid);
            }
            total += __popc(mask);
        }
        if (tid == 0) scnt = total;
    }
    __syncthreads();

    const int cnt = scnt;
    const float4* v4 = (const float4*)(v + (size_t)b * LL * DD);  // [1024][192]
    float4 acc = make_float4(0.f, 0.f, 0.f, 0.f);

    int t = 0;
    for (; t + 4 <= cnt; t += 4) {
        float a0 = svals[t + 0], a1 = svals[t + 1];
        float a2 = svals[t + 2], a3 = svals[t + 3];
        int j0 = sidx[t + 0], j1 = sidx[t + 1];
        int j2 = sidx[t + 2], j3 = sidx[t + 3];
        float4 w0 = v4[(size_t)j0 * 192 + tid];
        float4 w1 = v4[(size_t)j1 * 192 + tid];
        float4 w2 = v4[(size_t)j2 * 192 + tid];
        float4 w3 = v4[(size_t)j3 * 192 + tid];
        acc.x += a0 * w0.x; acc.y += a0 * w0.y; acc.z += a0 * w0.z; acc.w += a0 * w0.w;
        acc.x += a1 * w1.x; acc.y += a1 * w1.y; acc.z += a1 * w1.z; acc.w += a1 * w1.w;
        acc.x += a2 * w2.x; acc.y += a2 * w2.y; acc.z += a2 * w2.z; acc.w += a2 * w2.w;
        acc.x += a3 * w3.x; acc.y += a3 * w3.y; acc.z += a3 * w3.z; acc.w += a3 * w3.w;
    }
    for (; t < cnt; t++) {
        float a = svals[t];
        int j = sidx[t];
        float4 w = v4[(size_t)j * 192 + tid];
        acc.x += a * w.x; acc.y += a * w.y; acc.z += a * w.z; acc.w += a * w.w;
    }

    float4* o4 = (float4*)(out + ((size_t)b * LL + q) * DD);
    o4[tid] = acc;
}

// =================================================================
// launch
// =================================================================
extern "C" void kernel_launch(void* const* d_in, const int* in_sizes, int n_in,
                              void* d_out, int out_size)
{
    const float* q  = (const float*)d_in[0];
    const float* k  = (const float*)d_in[1];
    const float* v  = (const float*)d_in[2];
    const float* Wq = (const float*)d_in[3];
    const float* bq = (const float*)d_in[4];
    const float* Wk = (const float*)d_in[5];
    const float* bk = (const float*)d_in[6];

    const int OUT_N = BB * LL * DD;   // 6291456
    const int ATT_N = BB * LL * LL;   // 8388608

    float* outp = (float*)d_out;
    float* out_ptr = nullptr;   // nullptr -> kernel falls back to scratch
    float* attn_ptr = nullptr;

    if (out_size >= OUT_N + ATT_N) {
        out_ptr = outp;
        attn_ptr = outp + OUT_N;
    } else if (out_size == ATT_N) {
        attn_ptr = outp;          // attn-only output
    } else if (out_size >= OUT_N) {
        out_ptr = outp;           // output-only
    }

    // 1. zero the attn accumulator
    zero_attn_kernel<<<ATT_N / 1024, 1024>>>(attn_ptr);

    // 2. projections
    dim3 pg(DD / 128, (BB * LL) / 128);   // (6, 64)
    proj_kernel<<<pg, 256>>>(q, Wq, bq, 0);
    proj_kernel<<<pg, 256>>>(k, Wk, bk, 1);

    // 3. scores + sparsemax + head-mean
    dim3 ag(LL / 16, NH, BB);             // (64, 12, 8)
    attn_kernel<<<ag, 256>>>(attn_ptr);

    // 4. sparse output gather
    dim3 og(LL, BB);                      // (1024, 8)
    out_kernel<<<og, 192>>>(attn_ptr, v, out_ptr);
}

// round 10
// speedup vs baseline: 1.2324x; 1.2324x over previous
#include <cuda_runtime.h>

#define BB 8
#define LL 1024
#define DD 768
#define NH 12
#define DH 64

// ---------------- scratch (no cudaMalloc allowed) ----------------
__device__ float g_Qp[BB * LL * DD];   // projected Q  [B*L, 768]
__device__ float g_Kp[BB * LL * DD];   // projected K  [B*L, 768]
__device__ float g_Attn[BB * LL * LL]; // fallback attn scratch
__device__ float g_Out[BB * LL * DD];  // fallback out scratch

// =================================================================
// Projection GEMM:  C[m,n] = sum_k A[m,k] * W[n,k] + bias[n]
// =================================================================
__global__ __launch_bounds__(256, 2)
void proj_kernel(const float* __restrict__ A, const float* __restrict__ W,
                 const float* __restrict__ bias, int which)
{
    float* C = which ? g_Kp : g_Qp;
    __shared__ float As[8][128];
    __shared__ float Ws[8][128];

    const int tid = threadIdx.x;
    const int tx = tid & 15;
    const int ty = tid >> 4;
    const int m0 = blockIdx.y * 128;
    const int n0 = blockIdx.x * 128;

    const int lrow = tid >> 1;
    const int lcol = (tid & 1) * 4;

    float acc[8][8];
#pragma unroll
    for (int i = 0; i < 8; i++)
#pragma unroll
        for (int j = 0; j < 8; j++) acc[i][j] = 0.f;

    const float* Ag = A + (size_t)(m0 + lrow) * DD + lcol;
    const float* Wg = W + (size_t)(n0 + lrow) * DD + lcol;

    for (int k0 = 0; k0 < DD; k0 += 8) {
        float4 av = *(const float4*)(Ag + k0);
        float4 wv = *(const float4*)(Wg + k0);
        __syncthreads();
        As[lcol + 0][lrow] = av.x; As[lcol + 1][lrow] = av.y;
        As[lcol + 2][lrow] = av.z; As[lcol + 3][lrow] = av.w;
        Ws[lcol + 0][lrow] = wv.x; Ws[lcol + 1][lrow] = wv.y;
        Ws[lcol + 2][lrow] = wv.z; Ws[lcol + 3][lrow] = wv.w;
        __syncthreads();
#pragma unroll
        for (int k = 0; k < 8; k++) {
            float a[8], b[8];
            *(float4*)&a[0] = *(const float4*)&As[k][ty * 4];
            *(float4*)&a[4] = *(const float4*)&As[k][ty * 4 + 64];
            *(float4*)&b[0] = *(const float4*)&Ws[k][tx * 4];
            *(float4*)&b[4] = *(const float4*)&Ws[k][tx * 4 + 64];
#pragma unroll
            for (int i = 0; i < 8; i++)
#pragma unroll
                for (int j = 0; j < 8; j++) acc[i][j] += a[i] * b[j];
        }
    }

    float4 bv[2];
    bv[0] = *(const float4*)&bias[n0 + tx * 4];
    bv[1] = *(const float4*)&bias[n0 + tx * 4 + 64];

#pragma unroll
    for (int ih = 0; ih < 2; ih++)
#pragma unroll
        for (int i = 0; i < 4; i++) {
            int m = m0 + ty * 4 + i + ih * 64;
#pragma unroll
            for (int jh = 0; jh < 2; jh++) {
                float4 o;
                o.x = acc[ih * 4 + i][jh * 4 + 0] + bv[jh].x;
                o.y = acc[ih * 4 + i][jh * 4 + 1] + bv[jh].y;
                o.z = acc[ih * 4 + i][jh * 4 + 2] + bv[jh].z;
                o.w = acc[ih * 4 + i][jh * 4 + 3] + bv[jh].w;
                *(float4*)&C[(size_t)m * DD + n0 + tx * 4 + jh * 64] = o;
            }
        }
}

// =================================================================
// Zero the attn accumulator (vectorized)
// =================================================================
__global__ void zero_attn_kernel(float* p)
{
    float4* a = (float4*)(p ? p : g_Attn);
    size_t i = (size_t)blockIdx.x * blockDim.x + threadIdx.x;
    a[i] = make_float4(0.f, 0.f, 0.f, 0.f);
}

// =================================================================
// warp helpers
// =================================================================
__device__ __forceinline__ float warp_sum(float v)
{
#pragma unroll
    for (int o = 16; o > 0; o >>= 1) v += __shfl_xor_sync(0xffffffffu, v, o);
    return v;
}
__device__ __forceinline__ int warp_sum_i(int v)
{
#pragma unroll
    for (int o = 16; o > 0; o >>= 1) v += __shfl_xor_sync(0xffffffffu, v, o);
    return v;
}
__device__ __forceinline__ float warp_max(float v)
{
#pragma unroll
    for (int o = 16; o > 0; o >>= 1) v = fmaxf(v, __shfl_xor_sync(0xffffffffu, v, o));
    return v;
}

// =================================================================
// Attention kernel v2: per block (b, h, 16 q-rows), 256 threads.
// GEMM phase: warp w -> q-rows 4*(w&3)..+3, key-half (w>>2)*512.
//   Per 128-key tile: thread tile 4q x 4k, float4 LDS over d.
// Scores staged to smem (union with K buffers), reloaded so warp w
// owns full rows {w, w+8}; sparsemax via Newton fixed point;
// nonzeros scattered atomically into head-mean attn (scaled 1/12).
// =================================================================
#define KT_STRIDE 68                       // 64 + 4 pad (float4 conflict-free)
#define KT_FLOATS (2 * 128 * KT_STRIDE)    // 17408
#define SMEM_FLOATS (KT_FLOATS + 16 * 64)  // + Qs = 18432 floats = 73728 B

__global__ __launch_bounds__(256, 2)
void attn_kernel(float* __restrict__ attn_arg)
{
    float* attn = attn_arg ? attn_arg : g_Attn;

    extern __shared__ float sdyn[];
    float* Kt = sdyn;                  // [2][128][68]  (GEMM phase)
    float* Ss = sdyn;                  // [16][1024]    (union, after GEMM)
    float* Qs = sdyn + KT_FLOATS;      // [16][64]

    const int tid  = threadIdx.x;
    const int lane = tid & 31;
    const int warp = tid >> 5;        // 0..7
    const int g    = warp & 3;        // q row group (GEMM)
    const int H    = warp >> 2;       // key half (GEMM)
    const int qt = blockIdx.x;
    const int h  = blockIdx.y;
    const int b  = blockIdx.z;

    const float* Qp = g_Qp + ((size_t)b * LL + qt * 16) * DD + h * DH;
    const float* Kp = g_Kp + (size_t)b * LL * DD + h * DH;

    // load Q tile pre-scaled by 1/sqrt(64)=0.125 (exact)
    {
        int r = tid >> 4;
        int c = (tid & 15) * 4;
        float4 v = *(const float4*)(Qp + (size_t)r * DD + c);
        v.x *= 0.125f; v.y *= 0.125f; v.z *= 0.125f; v.w *= 0.125f;
        *(float4*)&Qs[r * 64 + c] = v;
    }

    float acc[4][16];
#pragma unroll
    for (int r = 0; r < 4; r++)
#pragma unroll
        for (int j = 0; j < 16; j++) acc[r][j] = 0.f;

#pragma unroll
    for (int pr = 0; pr < 4; pr++) {
        __syncthreads();
        // cooperative stage of 2 tiles (128 keys x 64 d each)
#pragma unroll
        for (int i = 0; i < 16; i++) {
            int idx = tid + 256 * i;          // 0..4095
            int hh  = idx >> 11;              // which half's tile
            int key = (idx >> 4) & 127;
            int c4  = (idx & 15) * 4;
            int gk  = hh * 512 + pr * 128 + key;
            float4 v = *(const float4*)(Kp + (size_t)gk * DD + c4);
            *(float4*)&Kt[hh * (128 * KT_STRIDE) + key * KT_STRIDE + c4] = v;
        }
        __syncthreads();

        const float* Kh = Kt + H * (128 * KT_STRIDE);
        const float* Qg = Qs + (g * 4) * 64;
#pragma unroll 8
        for (int d4 = 0; d4 < 16; d4++) {
            float4 q0 = *(const float4*)&Qg[0 * 64 + d4 * 4];
            float4 q1 = *(const float4*)&Qg[1 * 64 + d4 * 4];
            float4 q2 = *(const float4*)&Qg[2 * 64 + d4 * 4];
            float4 q3 = *(const float4*)&Qg[3 * 64 + d4 * 4];
            float4 k0 = *(const float4*)&Kh[(lane +  0) * KT_STRIDE + d4 * 4];
            float4 k1 = *(const float4*)&Kh[(lane + 32) * KT_STRIDE + d4 * 4];
            float4 k2 = *(const float4*)&Kh[(lane + 64) * KT_STRIDE + d4 * 4];
            float4 k3 = *(const float4*)&Kh[(lane + 96) * KT_STRIDE + d4 * 4];
#define DOT(r, j, qv, kv)                                           \
            acc[r][pr * 4 + j] += qv.x * kv.x; acc[r][pr * 4 + j] += qv.y * kv.y; \
            acc[r][pr * 4 + j] += qv.z * kv.z; acc[r][pr * 4 + j] += qv.w * kv.w;
            DOT(0,0,q0,k0) DOT(0,1,q0,k1) DOT(0,2,q0,k2) DOT(0,3,q0,k3)
            DOT(1,0,q1,k0) DOT(1,1,q1,k1) DOT(1,2,q1,k2) DOT(1,3,q1,k3)
            DOT(2,0,q2,k0) DOT(2,1,q2,k1) DOT(2,2,q2,k2) DOT(2,3,q2,k3)
            DOT(3,0,q3,k0) DOT(3,1,q3,k1) DOT(3,2,q3,k2) DOT(3,3,q3,k3)
#undef DOT
        }
    }

    // ---- stage scores to smem (overwrites Kt) ----
    __syncthreads();
#pragma unroll
    for (int r = 0; r < 4; r++) {
        int row = g * 4 + r;
#pragma unroll
        for (int t = 0; t < 4; t++)
#pragma unroll
            for (int jj = 0; jj < 4; jj++) {
                int col = H * 512 + t * 128 + jj * 32 + lane;
                Ss[row * 1024 + col] = acc[r][t * 4 + jj];
            }
    }
    __syncthreads();

    // ---- reload: warp owns full rows {warp, warp+8} ----
    float z0[32], z1[32];
    {
        const float* r0 = Ss + (size_t)warp * 1024;
        const float* r1 = Ss + (size_t)(warp + 8) * 1024;
#pragma unroll
        for (int t = 0; t < 8; t++) {
            float4 a = *(const float4*)&r0[t * 128 + lane * 4];
            float4 c = *(const float4*)&r1[t * 128 + lane * 4];
            z0[t * 4 + 0] = a.x; z0[t * 4 + 1] = a.y;
            z0[t * 4 + 2] = a.z; z0[t * 4 + 3] = a.w;
            z1[t * 4 + 0] = c.x; z1[t * 4 + 1] = c.y;
            z1[t * 4 + 2] = c.z; z1[t * 4 + 3] = c.w;
        }
    }

    // ---- sparsemax via Newton fixed point: tau <- (S-1)/k over {z>tau} ----
    float m0 = z0[0], m1 = z1[0];
#pragma unroll
    for (int i = 1; i < 32; i++) { m0 = fmaxf(m0, z0[i]); m1 = fmaxf(m1, z1[i]); }
    m0 = warp_max(m0);
    m1 = warp_max(m1);

    float t0 = m0 - 1.f, t1 = m1 - 1.f;
    for (int it = 0; it < 32; it++) {
        float S0 = 0.f, S1 = 0.f;
        int   k0 = 0,   k1 = 0;
#pragma unroll
        for (int i = 0; i < 32; i++) {
            if (z0[i] > t0) { S0 += z0[i]; k0++; }
            if (z1[i] > t1) { S1 += z1[i]; k1++; }
        }
        S0 = warp_sum(S0); S1 = warp_sum(S1);
        k0 = warp_sum_i(k0); k1 = warp_sum_i(k1);
        float n0 = __fdividef(S0 - 1.f, (float)k0);
        float n1 = __fdividef(S1 - 1.f, (float)k1);
        bool done = (n0 == t0) && (n1 == t1);   // uniform across warp
        t0 = n0; t1 = n1;
        if (done) break;
    }

    // ---- scatter nonzeros into head-mean attn ----
    const float inv12 = 1.f / 12.f;
    float* arow0 = attn + ((size_t)b * LL + qt * 16 + warp) * LL;
    float* arow1 = arow0 + (size_t)8 * LL;
#pragma unroll
    for (int i = 0; i < 32; i++) {
        int col = (i >> 2) * 128 + lane * 4 + (i & 3);
        float a = z0[i] - t0;
        if (a > 0.f) atomicAdd(&arow0[col], a * inv12);
        float c = z1[i] - t1;
        if (c > 0.f) atomicAdd(&arow1[col], c * inv12);
    }
}

// =================================================================
// Output kernel: out[b,q,:] = sum_j attn[b,q,j] * v[b,j,:]
// =================================================================
__global__ __launch_bounds__(192)
void out_kernel(const float* __restrict__ attn_arg, const float* __restrict__ v,
                float* __restrict__ out_arg)
{
    const float* attn = attn_arg ? attn_arg : g_Attn;
    float* out = out_arg ? out_arg : g_Out;

    __shared__ float srow[1024];
    __shared__ float svals[1024];
    __shared__ unsigned short sidx[1024];
    __shared__ int scnt;

    const int tid = threadIdx.x;
    const int q = blockIdx.x;
    const int b = blockIdx.y;

    const float* arow = attn + ((size_t)b * LL + q) * LL;
    for (int i = tid; i < 1024; i += 192) srow[i] = arow[i];
    __syncthreads();

    if (tid < 32) {
        int total = 0;
        for (int base = 0; base < 1024; base += 32) {
            float val = srow[base + tid];
            unsigned mask = __ballot_sync(0xffffffffu, val != 0.f);
            if (val != 0.f) {
                int pos = total + __popc(mask & ((1u << tid) - 1u));
                svals[pos] = val;
                sidx[pos] = (unsigned short)(base + tid);
            }
            total += __popc(mask);
        }
        if (tid == 0) scnt = total;
    }
    __syncthreads();

    const int cnt = scnt;
    const float4* v4 = (const float4*)(v + (size_t)b * LL * DD);
    float4 acc = make_float4(0.f, 0.f, 0.f, 0.f);

    int t = 0;
    for (; t + 4 <= cnt; t += 4) {
        float a0 = svals[t + 0], a1 = svals[t + 1];
        float a2 = svals[t + 2], a3 = svals[t + 3];
        int j0 = sidx[t + 0], j1 = sidx[t + 1];
        int j2 = sidx[t + 2], j3 = sidx[t + 3];
        float4 w0 = v4[(size_t)j0 * 192 + tid];
        float4 w1 = v4[(size_t)j1 * 192 + tid];
        float4 w2 = v4[(size_t)j2 * 192 + tid];
        float4 w3 = v4[(size_t)j3 * 192 + tid];
        acc.x += a0 * w0.x; acc.y += a0 * w0.y; acc.z += a0 * w0.z; acc.w += a0 * w0.w;
        acc.x += a1 * w1.x; acc.y += a1 * w1.y; acc.z += a1 * w1.z; acc.w += a1 * w1.w;
        acc.x += a2 * w2.x; acc.y += a2 * w2.y; acc.z += a2 * w2.z; acc.w += a2 * w2.w;
        acc.x += a3 * w3.x; acc.y += a3 * w3.y; acc.z += a3 * w3.z; acc.w += a3 * w3.w;
    }
    for (; t < cnt; t++) {
        float a = svals[t];
        int j = sidx[t];
        float4 w = v4[(size_t)j * 192 + tid];
        acc.x += a * w.x; acc.y += a * w.y; acc.z += a * w.z; acc.w += a * w.w;
    }

    float4* o4 = (float4*)(out + ((size_t)b * LL + q) * DD);
    o4[tid] = acc;
}

// =================================================================
// launch
// =================================================================
extern "C" void kernel_launch(void* const* d_in, const int* in_sizes, int n_in,
                              void* d_out, int out_size)
{
    const float* q  = (const float*)d_in[0];
    const float* k  = (const float*)d_in[1];
    const float* v  = (const float*)d_in[2];
    const float* Wq = (const float*)d_in[3];
    const float* bq = (const float*)d_in[4];
    const float* Wk = (const float*)d_in[5];
    const float* bk = (const float*)d_in[6];

    const int OUT_N = BB * LL * DD;   // 6291456
    const int ATT_N = BB * LL * LL;   // 8388608

    float* outp = (float*)d_out;
    float* out_ptr = nullptr;
    float* attn_ptr = nullptr;

    if (out_size >= OUT_N + ATT_N) {
        out_ptr = outp;
        attn_ptr = outp + OUT_N;
    } else if (out_size == ATT_N) {
        attn_ptr = outp;
    } else if (out_size >= OUT_N) {
        out_ptr = outp;
    }

    const int SMEM_BYTES = SMEM_FLOATS * 4;   // 73728
    cudaFuncSetAttribute(attn_kernel,
                         cudaFuncAttributeMaxDynamicSharedMemorySize, SMEM_BYTES);

    // 1. zero the attn accumulator (float4)
    zero_attn_kernel<<<ATT_N / 4 / 256, 256>>>(attn_ptr);

    // 2. projections
    dim3 pg(DD / 128, (BB * LL) / 128);   // (6, 64)
    proj_kernel<<<pg, 256>>>(q, Wq, bq, 0);
    proj_kernel<<<pg, 256>>>(k, Wk, bk, 1);

    // 3. scores + sparsemax + head-mean
    dim3 ag(LL / 16, NH, BB);             // (64, 12, 8)
    attn_kernel<<<ag, 256, SMEM_BYTES>>>(attn_ptr);

    // 4. sparse output gather
    dim3 og(LL, BB);                      // (1024, 8)
    out_kernel<<<og, 192>>>(attn_ptr, v, out_ptr);
}

// round 11
// speedup vs baseline: 1.2329x; 1.0004x over previous
#include <cuda_runtime.h>

#define BB 8
#define LL 1024
#define DD 768
#define NH 12
#define DH 64

// ---------------- scratch (no cudaMalloc allowed) ----------------
__device__ float g_Qp[BB * LL * DD];   // projected Q  [B*L, 768]
__device__ float g_Kp[BB * LL * DD];   // projected K  [B*L, 768]
__device__ float g_Attn[BB * LL * LL]; // fallback attn scratch
__device__ float g_Out[BB * LL * DD];  // fallback out scratch

// =================================================================
// Projection GEMM:  C[m,n] = sum_k A[m,k] * W[n,k] + bias[n]
// =================================================================
__global__ __launch_bounds__(256, 2)
void proj_kernel(const float* __restrict__ A, const float* __restrict__ W,
                 const float* __restrict__ bias, int which)
{
    float* C = which ? g_Kp : g_Qp;
    __shared__ float As[8][128];
    __shared__ float Ws[8][128];

    const int tid = threadIdx.x;
    const int tx = tid & 15;
    const int ty = tid >> 4;
    const int m0 = blockIdx.y * 128;
    const int n0 = blockIdx.x * 128;

    const int lrow = tid >> 1;
    const int lcol = (tid & 1) * 4;

    float acc[8][8];
#pragma unroll
    for (int i = 0; i < 8; i++)
#pragma unroll
        for (int j = 0; j < 8; j++) acc[i][j] = 0.f;

    const float* Ag = A + (size_t)(m0 + lrow) * DD + lcol;
    const float* Wg = W + (size_t)(n0 + lrow) * DD + lcol;

    for (int k0 = 0; k0 < DD; k0 += 8) {
        float4 av = *(const float4*)(Ag + k0);
        float4 wv = *(const float4*)(Wg + k0);
        __syncthreads();
        As[lcol + 0][lrow] = av.x; As[lcol + 1][lrow] = av.y;
        As[lcol + 2][lrow] = av.z; As[lcol + 3][lrow] = av.w;
        Ws[lcol + 0][lrow] = wv.x; Ws[lcol + 1][lrow] = wv.y;
        Ws[lcol + 2][lrow] = wv.z; Ws[lcol + 3][lrow] = wv.w;
        __syncthreads();
#pragma unroll
        for (int k = 0; k < 8; k++) {
            float a[8], b[8];
            *(float4*)&a[0] = *(const float4*)&As[k][ty * 4];
            *(float4*)&a[4] = *(const float4*)&As[k][ty * 4 + 64];
            *(float4*)&b[0] = *(const float4*)&Ws[k][tx * 4];
            *(float4*)&b[4] = *(const float4*)&Ws[k][tx * 4 + 64];
#pragma unroll
            for (int i = 0; i < 8; i++)
#pragma unroll
                for (int j = 0; j < 8; j++) acc[i][j] += a[i] * b[j];
        }
    }

    float4 bv[2];
    bv[0] = *(const float4*)&bias[n0 + tx * 4];
    bv[1] = *(const float4*)&bias[n0 + tx * 4 + 64];

#pragma unroll
    for (int ih = 0; ih < 2; ih++)
#pragma unroll
        for (int i = 0; i < 4; i++) {
            int m = m0 + ty * 4 + i + ih * 64;
#pragma unroll
            for (int jh = 0; jh < 2; jh++) {
                float4 o;
                o.x = acc[ih * 4 + i][jh * 4 + 0] + bv[jh].x;
                o.y = acc[ih * 4 + i][jh * 4 + 1] + bv[jh].y;
                o.z = acc[ih * 4 + i][jh * 4 + 2] + bv[jh].z;
                o.w = acc[ih * 4 + i][jh * 4 + 3] + bv[jh].w;
                *(float4*)&C[(size_t)m * DD + n0 + tx * 4 + jh * 64] = o;
            }
        }
}

// =================================================================
// Zero the attn accumulator (vectorized)
// =================================================================
__global__ void zero_attn_kernel(float* p)
{
    float4* a = (float4*)(p ? p : g_Attn);
    size_t i = (size_t)blockIdx.x * blockDim.x + threadIdx.x;
    a[i] = make_float4(0.f, 0.f, 0.f, 0.f);
}

// =================================================================
// warp helpers
// =================================================================
__device__ __forceinline__ float warp_sum(float v)
{
#pragma unroll
    for (int o = 16; o > 0; o >>= 1) v += __shfl_xor_sync(0xffffffffu, v, o);
    return v;
}
__device__ __forceinline__ int warp_sum_i(int v)
{
#pragma unroll
    for (int o = 16; o > 0; o >>= 1) v += __shfl_xor_sync(0xffffffffu, v, o);
    return v;
}
__device__ __forceinline__ float warp_max(float v)
{
#pragma unroll
    for (int o = 16; o > 0; o >>= 1) v = fmaxf(v, __shfl_xor_sync(0xffffffffu, v, o));
    return v;
}

// =================================================================
// Attention kernel v2: per block (b, h, 16 q-rows), 256 threads.
// GEMM phase: warp w -> q-rows 4*(w&3)..+3, key-half (w>>2)*512.
//   Per 128-key tile: thread tile 4q x 4k, float4 LDS over d.
// Scores staged to smem (union with K buffers), reloaded so warp w
// owns full rows {w, w+8}; sparsemax via Newton fixed point;
// nonzeros scattered atomically into head-mean attn (scaled 1/12).
// =================================================================
#define KT_STRIDE 68                       // 64 + 4 pad (float4 conflict-free)
#define KT_FLOATS (2 * 128 * KT_STRIDE)    // 17408
#define SMEM_FLOATS (KT_FLOATS + 16 * 64)  // + Qs = 18432 floats = 73728 B

__global__ __launch_bounds__(256, 2)
void attn_kernel(float* __restrict__ attn_arg)
{
    float* attn = attn_arg ? attn_arg : g_Attn;

    extern __shared__ float sdyn[];
    float* Kt = sdyn;                  // [2][128][68]  (GEMM phase)
    float* Ss = sdyn;                  // [16][1024]    (union, after GEMM)
    float* Qs = sdyn + KT_FLOATS;      // [16][64]

    const int tid  = threadIdx.x;
    const int lane = tid & 31;
    const int warp = tid >> 5;        // 0..7
    const int g    = warp & 3;        // q row group (GEMM)
    const int H    = warp >> 2;       // key half (GEMM)
    const int qt = blockIdx.x;
    const int h  = blockIdx.y;
    const int b  = blockIdx.z;

    const float* Qp = g_Qp + ((size_t)b * LL + qt * 16) * DD + h * DH;
    const float* Kp = g_Kp + (size_t)b * LL * DD + h * DH;

    // load Q tile pre-scaled by 1/sqrt(64)=0.125 (exact)
    {
        int r = tid >> 4;
        int c = (tid & 15) * 4;
        float4 v = *(const float4*)(Qp + (size_t)r * DD + c);
        v.x *= 0.125f; v.y *= 0.125f; v.z *= 0.125f; v.w *= 0.125f;
        *(float4*)&Qs[r * 64 + c] = v;
    }

    float acc[4][16];
#pragma unroll
    for (int r = 0; r < 4; r++)
#pragma unroll
        for (int j = 0; j < 16; j++) acc[r][j] = 0.f;

#pragma unroll
    for (int pr = 0; pr < 4; pr++) {
        __syncthreads();
        // cooperative stage of 2 tiles (128 keys x 64 d each)
#pragma unroll
        for (int i = 0; i < 16; i++) {
            int idx = tid + 256 * i;          // 0..4095
            int hh  = idx >> 11;              // which half's tile
            int key = (idx >> 4) & 127;
            int c4  = (idx & 15) * 4;
            int gk  = hh * 512 + pr * 128 + key;
            float4 v = *(const float4*)(Kp + (size_t)gk * DD + c4);
            *(float4*)&Kt[hh * (128 * KT_STRIDE) + key * KT_STRIDE + c4] = v;
        }
        __syncthreads();

        const float* Kh = Kt + H * (128 * KT_STRIDE);
        const float* Qg = Qs + (g * 4) * 64;
#pragma unroll 8
        for (int d4 = 0; d4 < 16; d4++) {
            float4 q0 = *(const float4*)&Qg[0 * 64 + d4 * 4];
            float4 q1 = *(const float4*)&Qg[1 * 64 + d4 * 4];
            float4 q2 = *(const float4*)&Qg[2 * 64 + d4 * 4];
            float4 q3 = *(const float4*)&Qg[3 * 64 + d4 * 4];
            float4 k0 = *(const float4*)&Kh[(lane +  0) * KT_STRIDE + d4 * 4];
            float4 k1 = *(const float4*)&Kh[(lane + 32) * KT_STRIDE + d4 * 4];
            float4 k2 = *(const float4*)&Kh[(lane + 64) * KT_STRIDE + d4 * 4];
            float4 k3 = *(const float4*)&Kh[(lane + 96) * KT_STRIDE + d4 * 4];
#define DOT(r, j, qv, kv)                                           \
            acc[r][pr * 4 + j] += qv.x * kv.x; acc[r][pr * 4 + j] += qv.y * kv.y; \
            acc[r][pr * 4 + j] += qv.z * kv.z; acc[r][pr * 4 + j] += qv.w * kv.w;
            DOT(0,0,q0,k0) DOT(0,1,q0,k1) DOT(0,2,q0,k2) DOT(0,3,q0,k3)
            DOT(1,0,q1,k0) DOT(1,1,q1,k1) DOT(1,2,q1,k2) DOT(1,3,q1,k3)
            DOT(2,0,q2,k0) DOT(2,1,q2,k1) DOT(2,2,q2,k2) DOT(2,3,q2,k3)
            DOT(3,0,q3,k0) DOT(3,1,q3,k1) DOT(3,2,q3,k2) DOT(3,3,q3,k3)
#undef DOT
        }
    }

    // ---- stage scores to smem (overwrites Kt) ----
    __syncthreads();
#pragma unroll
    for (int r = 0; r < 4; r++) {
        int row = g * 4 + r;
#pragma unroll
        for (int t = 0; t < 4; t++)
#pragma unroll
            for (int jj = 0; jj < 4; jj++) {
                int col = H * 512 + t * 128 + jj * 32 + lane;
                Ss[row * 1024 + col] = acc[r][t * 4 + jj];
            }
    }
    __syncthreads();

    // ---- reload: warp owns full rows {warp, warp+8} ----
    float z0[32], z1[32];
    {
        const float* r0 = Ss + (size_t)warp * 1024;
        const float* r1 = Ss + (size_t)(warp + 8) * 1024;
#pragma unroll
        for (int t = 0; t < 8; t++) {
            float4 a = *(const float4*)&r0[t * 128 + lane * 4];
            float4 c = *(const float4*)&r1[t * 128 + lane * 4];
            z0[t * 4 + 0] = a.x; z0[t * 4 + 1] = a.y;
            z0[t * 4 + 2] = a.z; z0[t * 4 + 3] = a.w;
            z1[t * 4 + 0] = c.x; z1[t * 4 + 1] = c.y;
            z1[t * 4 + 2] = c.z; z1[t * 4 + 3] = c.w;
        }
    }

    // ---- sparsemax via Newton fixed point: tau <- (S-1)/k over {z>tau} ----
    float m0 = z0[0], m1 = z1[0];
#pragma unroll
    for (int i = 1; i < 32; i++) { m0 = fmaxf(m0, z0[i]); m1 = fmaxf(m1, z1[i]); }
    m0 = warp_max(m0);
    m1 = warp_max(m1);

    float t0 = m0 - 1.f, t1 = m1 - 1.f;
    for (int it = 0; it < 32; it++) {
        float S0 = 0.f, S1 = 0.f;
        int   k0 = 0,   k1 = 0;
#pragma unroll
        for (int i = 0; i < 32; i++) {
            if (z0[i] > t0) { S0 += z0[i]; k0++; }
            if (z1[i] > t1) { S1 += z1[i]; k1++; }
        }
        S0 = warp_sum(S0); S1 = warp_sum(S1);
        k0 = warp_sum_i(k0); k1 = warp_sum_i(k1);
        float n0 = __fdividef(S0 - 1.f, (float)k0);
        float n1 = __fdividef(S1 - 1.f, (float)k1);
        bool done = (n0 == t0) && (n1 == t1);   // uniform across warp
        t0 = n0; t1 = n1;
        if (done) break;
    }

    // ---- scatter nonzeros into head-mean attn ----
    const float inv12 = 1.f / 12.f;
    float* arow0 = attn + ((size_t)b * LL + qt * 16 + warp) * LL;
    float* arow1 = arow0 + (size_t)8 * LL;
#pragma unroll
    for (int i = 0; i < 32; i++) {
        int col = (i >> 2) * 128 + lane * 4 + (i & 3);
        float a = z0[i] - t0;
        if (a > 0.f) atomicAdd(&arow0[col], a * inv12);
        float c = z1[i] - t1;
        if (c > 0.f) atomicAdd(&arow1[col], c * inv12);
    }
}

// =================================================================
// Output kernel: out[b,q,:] = sum_j attn[b,q,j] * v[b,j,:]
// =================================================================
__global__ __launch_bounds__(192)
void out_kernel(const float* __restrict__ attn_arg, const float* __restrict__ v,
                float* __restrict__ out_arg)
{
    const float* attn = attn_arg ? attn_arg : g_Attn;
    float* out = out_arg ? out_arg : g_Out;

    __shared__ float srow[1024];
    __shared__ float svals[1024];
    __shared__ unsigned short sidx[1024];
    __shared__ int scnt;

    const int tid = threadIdx.x;
    const int q = blockIdx.x;
    const int b = blockIdx.y;

    const float* arow = attn + ((size_t)b * LL + q) * LL;
    for (int i = tid; i < 1024; i += 192) srow[i] = arow[i];
    __syncthreads();

    if (tid < 32) {
        int total = 0;
        for (int base = 0; base < 1024; base += 32) {
            float val = srow[base + tid];
            unsigned mask = __ballot_sync(0xffffffffu, val != 0.f);
            if (val != 0.f) {
                int pos = total + __popc(mask & ((1u << tid) - 1u));
                svals[pos] = val;
                sidx[pos] = (unsigned short)(base + tid);
            }
            total += __popc(mask);
        }
        if (tid == 0) scnt = total;
    }
    __syncthreads();

    const int cnt = scnt;
    const float4* v4 = (const float4*)(v + (size_t)b * LL * DD);
    float4 acc = make_float4(0.f, 0.f, 0.f, 0.f);

    int t = 0;
    for (; t + 4 <= cnt; t += 4) {
        float a0 = svals[t + 0], a1 = svals[t + 1];
        float a2 = svals[t + 2], a3 = svals[t + 3];
        int j0 = sidx[t + 0], j1 = sidx[t + 1];
        int j2 = sidx[t + 2], j3 = sidx[t + 3];
        float4 w0 = v4[(size_t)j0 * 192 + tid];
        float4 w1 = v4[(size_t)j1 * 192 + tid];
        float4 w2 = v4[(size_t)j2 * 192 + tid];
        float4 w3 = v4[(size_t)j3 * 192 + tid];
        acc.x += a0 * w0.x; acc.y += a0 * w0.y; acc.z += a0 * w0.z; acc.w += a0 * w0.w;
        acc.x += a1 * w1.x; acc.y += a1 * w1.y; acc.z += a1 * w1.z; acc.w += a1 * w1.w;
        acc.x += a2 * w2.x; acc.y += a2 * w2.y; acc.z += a2 * w2.z; acc.w += a2 * w2.w;
        acc.x += a3 * w3.x; acc.y += a3 * w3.y; acc.z += a3 * w3.z; acc.w += a3 * w3.w;
    }
    for (; t < cnt; t++) {
        float a = svals[t];
        int j = sidx[t];
        float4 w = v4[(size_t)j * 192 + tid];
        acc.x += a * w.x; acc.y += a * w.y; acc.z += a * w.z; acc.w += a * w.w;
    }

    float4* o4 = (float4*)(out + ((size_t)b * LL + q) * DD);
    o4[tid] = acc;
}

// =================================================================
// launch
// =================================================================
extern "C" void kernel_launch(void* const* d_in, const int* in_sizes, int n_in,
                              void* d_out, int out_size)
{
    const float* q  = (const float*)d_in[0];
    const float* k  = (const float*)d_in[1];
    const float* v  = (const float*)d_in[2];
    const float* Wq = (const float*)d_in[3];
    const float* bq = (const float*)d_in[4];
    const float* Wk = (const float*)d_in[5];
    const float* bk = (const float*)d_in[6];

    const int OUT_N = BB * LL * DD;   // 6291456
    const int ATT_N = BB * LL * LL;   // 8388608

    float* outp = (float*)d_out;
    float* out_ptr = nullptr;
    float* attn_ptr = nullptr;

    if (out_size >= OUT_N + ATT_N) {
        out_ptr = outp;
        attn_ptr = outp + OUT_N;
    } else if (out_size == ATT_N) {
        attn_ptr = outp;
    } else if (out_size >= OUT_N) {
        out_ptr = outp;
    }

    const int SMEM_BYTES = SMEM_FLOATS * 4;   // 73728
    cudaFuncSetAttribute(attn_kernel,
                         cudaFuncAttributeMaxDynamicSharedMemorySize, SMEM_BYTES);

    // 1. zero the attn accumulator (float4)
    zero_attn_kernel<<<ATT_N / 4 / 256, 256>>>(attn_ptr);

    // 2. projections
    dim3 pg(DD / 128, (BB * LL) / 128);   // (6, 64)
    proj_kernel<<<pg, 256>>>(q, Wq, bq, 0);
    proj_kernel<<<pg, 256>>>(k, Wk, bk, 1);

    // 3. scores + sparsemax + head-mean
    dim3 ag(LL / 16, NH, BB);             // (64, 12, 8)
    attn_kernel<<<ag, 256, SMEM_BYTES>>>(attn_ptr);

    // 4. sparse output gather
    dim3 og(LL, BB);                      // (1024, 8)
    out_kernel<<<og, 192>>>(attn_ptr, v, out_ptr);
}

// round 12
// speedup vs baseline: 1.2332x; 1.0003x over previous
#include <cuda_runtime.h>

#define BB 8
#define LL 1024
#define DD 768
#define NH 12
#define DH 64

// ---------------- scratch (no cudaMalloc allowed) ----------------
__device__ float g_Qp[BB * LL * DD];   // projected Q  [B*L, 768]
__device__ float g_Kp[BB * LL * DD];   // projected K  [B*L, 768]
__device__ float g_Attn[BB * LL * LL]; // fallback attn scratch
__device__ float g_Out[BB * LL * DD];  // fallback out scratch

// =================================================================
// Projection GEMM:  C[m,n] = sum_k A[m,k] * W[n,k] + bias[n]
// =================================================================
__global__ __launch_bounds__(256, 2)
void proj_kernel(const float* __restrict__ A, const float* __restrict__ W,
                 const float* __restrict__ bias, int which)
{
    float* C = which ? g_Kp : g_Qp;
    __shared__ float As[8][128];
    __shared__ float Ws[8][128];

    const int tid = threadIdx.x;
    const int tx = tid & 15;
    const int ty = tid >> 4;
    const int m0 = blockIdx.y * 128;
    const int n0 = blockIdx.x * 128;

    const int lrow = tid >> 1;
    const int lcol = (tid & 1) * 4;

    float acc[8][8];
#pragma unroll
    for (int i = 0; i < 8; i++)
#pragma unroll
        for (int j = 0; j < 8; j++) acc[i][j] = 0.f;

    const float* Ag = A + (size_t)(m0 + lrow) * DD + lcol;
    const float* Wg = W + (size_t)(n0 + lrow) * DD + lcol;

    for (int k0 = 0; k0 < DD; k0 += 8) {
        float4 av = *(const float4*)(Ag + k0);
        float4 wv = *(const float4*)(Wg + k0);
        __syncthreads();
        As[lcol + 0][lrow] = av.x; As[lcol + 1][lrow] = av.y;
        As[lcol + 2][lrow] = av.z; As[lcol + 3][lrow] = av.w;
        Ws[lcol + 0][lrow] = wv.x; Ws[lcol + 1][lrow] = wv.y;
        Ws[lcol + 2][lrow] = wv.z; Ws[lcol + 3][lrow] = wv.w;
        __syncthreads();
#pragma unroll
        for (int k = 0; k < 8; k++) {
            float a[8], b[8];
            *(float4*)&a[0] = *(const float4*)&As[k][ty * 4];
            *(float4*)&a[4] = *(const float4*)&As[k][ty * 4 + 64];
            *(float4*)&b[0] = *(const float4*)&Ws[k][tx * 4];
            *(float4*)&b[4] = *(const float4*)&Ws[k][tx * 4 + 64];
#pragma unroll
            for (int i = 0; i < 8; i++)
#pragma unroll
                for (int j = 0; j < 8; j++) acc[i][j] += a[i] * b[j];
        }
    }

    float4 bv[2];
    bv[0] = *(const float4*)&bias[n0 + tx * 4];
    bv[1] = *(const float4*)&bias[n0 + tx * 4 + 64];

#pragma unroll
    for (int ih = 0; ih < 2; ih++)
#pragma unroll
        for (int i = 0; i < 4; i++) {
            int m = m0 + ty * 4 + i + ih * 64;
#pragma unroll
            for (int jh = 0; jh < 2; jh++) {
                float4 o;
                o.x = acc[ih * 4 + i][jh * 4 + 0] + bv[jh].x;
                o.y = acc[ih * 4 + i][jh * 4 + 1] + bv[jh].y;
                o.z = acc[ih * 4 + i][jh * 4 + 2] + bv[jh].z;
                o.w = acc[ih * 4 + i][jh * 4 + 3] + bv[jh].w;
                *(float4*)&C[(size_t)m * DD + n0 + tx * 4 + jh * 64] = o;
            }
        }
}

// =================================================================
// Zero the attn accumulator (vectorized)
// =================================================================
__global__ void zero_attn_kernel(float* p)
{
    float4* a = (float4*)(p ? p : g_Attn);
    size_t i = (size_t)blockIdx.x * blockDim.x + threadIdx.x;
    a[i] = make_float4(0.f, 0.f, 0.f, 0.f);
}

// =================================================================
// warp helpers
// =================================================================
__device__ __forceinline__ float warp_sum(float v)
{
#pragma unroll
    for (int o = 16; o > 0; o >>= 1) v += __shfl_xor_sync(0xffffffffu, v, o);
    return v;
}
__device__ __forceinline__ int warp_sum_i(int v)
{
#pragma unroll
    for (int o = 16; o > 0; o >>= 1) v += __shfl_xor_sync(0xffffffffu, v, o);
    return v;
}
__device__ __forceinline__ float warp_max(float v)
{
#pragma unroll
    for (int o = 16; o > 0; o >>= 1) v = fmaxf(v, __shfl_xor_sync(0xffffffffu, v, o));
    return v;
}

// =================================================================
// Attention kernel v2: per block (b, h, 16 q-rows), 256 threads.
// GEMM phase: warp w -> q-rows 4*(w&3)..+3, key-half (w>>2)*512.
//   Per 128-key tile: thread tile 4q x 4k, float4 LDS over d.
// Scores staged to smem (union with K buffers), reloaded so warp w
// owns full rows {w, w+8}; sparsemax via Newton fixed point;
// nonzeros scattered atomically into head-mean attn (scaled 1/12).
// =================================================================
#define KT_STRIDE 68                       // 64 + 4 pad (float4 conflict-free)
#define KT_FLOATS (2 * 128 * KT_STRIDE)    // 17408
#define SMEM_FLOATS (KT_FLOATS + 16 * 64)  // + Qs = 18432 floats = 73728 B

__global__ __launch_bounds__(256, 2)
void attn_kernel(float* __restrict__ attn_arg)
{
    float* attn = attn_arg ? attn_arg : g_Attn;

    extern __shared__ float sdyn[];
    float* Kt = sdyn;                  // [2][128][68]  (GEMM phase)
    float* Ss = sdyn;                  // [16][1024]    (union, after GEMM)
    float* Qs = sdyn + KT_FLOATS;      // [16][64]

    const int tid  = threadIdx.x;
    const int lane = tid & 31;
    const int warp = tid >> 5;        // 0..7
    const int g    = warp & 3;        // q row group (GEMM)
    const int H    = warp >> 2;       // key half (GEMM)
    const int qt = blockIdx.x;
    const int h  = blockIdx.y;
    const int b  = blockIdx.z;

    const float* Qp = g_Qp + ((size_t)b * LL + qt * 16) * DD + h * DH;
    const float* Kp = g_Kp + (size_t)b * LL * DD + h * DH;

    // load Q tile pre-scaled by 1/sqrt(64)=0.125 (exact)
    {
        int r = tid >> 4;
        int c = (tid & 15) * 4;
        float4 v = *(const float4*)(Qp + (size_t)r * DD + c);
        v.x *= 0.125f; v.y *= 0.125f; v.z *= 0.125f; v.w *= 0.125f;
        *(float4*)&Qs[r * 64 + c] = v;
    }

    float acc[4][16];
#pragma unroll
    for (int r = 0; r < 4; r++)
#pragma unroll
        for (int j = 0; j < 16; j++) acc[r][j] = 0.f;

#pragma unroll
    for (int pr = 0; pr < 4; pr++) {
        __syncthreads();
        // cooperative stage of 2 tiles (128 keys x 64 d each)
#pragma unroll
        for (int i = 0; i < 16; i++) {
            int idx = tid + 256 * i;          // 0..4095
            int hh  = idx >> 11;              // which half's tile
            int key = (idx >> 4) & 127;
            int c4  = (idx & 15) * 4;
            int gk  = hh * 512 + pr * 128 + key;
            float4 v = *(const float4*)(Kp + (size_t)gk * DD + c4);
            *(float4*)&Kt[hh * (128 * KT_STRIDE) + key * KT_STRIDE + c4] = v;
        }
        __syncthreads();

        const float* Kh = Kt + H * (128 * KT_STRIDE);
        const float* Qg = Qs + (g * 4) * 64;
#pragma unroll 8
        for (int d4 = 0; d4 < 16; d4++) {
            float4 q0 = *(const float4*)&Qg[0 * 64 + d4 * 4];
            float4 q1 = *(const float4*)&Qg[1 * 64 + d4 * 4];
            float4 q2 = *(const float4*)&Qg[2 * 64 + d4 * 4];
            float4 q3 = *(const float4*)&Qg[3 * 64 + d4 * 4];
            float4 k0 = *(const float4*)&Kh[(lane +  0) * KT_STRIDE + d4 * 4];
            float4 k1 = *(const float4*)&Kh[(lane + 32) * KT_STRIDE + d4 * 4];
            float4 k2 = *(const float4*)&Kh[(lane + 64) * KT_STRIDE + d4 * 4];
            float4 k3 = *(const float4*)&Kh[(lane + 96) * KT_STRIDE + d4 * 4];
#define DOT(r, j, qv, kv)                                           \
            acc[r][pr * 4 + j] += qv.x * kv.x; acc[r][pr * 4 + j] += qv.y * kv.y; \
            acc[r][pr * 4 + j] += qv.z * kv.z; acc[r][pr * 4 + j] += qv.w * kv.w;
            DOT(0,0,q0,k0) DOT(0,1,q0,k1) DOT(0,2,q0,k2) DOT(0,3,q0,k3)
            DOT(1,0,q1,k0) DOT(1,1,q1,k1) DOT(1,2,q1,k2) DOT(1,3,q1,k3)
            DOT(2,0,q2,k0) DOT(2,1,q2,k1) DOT(2,2,q2,k2) DOT(2,3,q2,k3)
            DOT(3,0,q3,k0) DOT(3,1,q3,k1) DOT(3,2,q3,k2) DOT(3,3,q3,k3)
#undef DOT
        }
    }

    // ---- stage scores to smem (overwrites Kt) ----
    __syncthreads();
#pragma unroll
    for (int r = 0; r < 4; r++) {
        int row = g * 4 + r;
#pragma unroll
        for (int t = 0; t < 4; t++)
#pragma unroll
            for (int jj = 0; jj < 4; jj++) {
                int col = H * 512 + t * 128 + jj * 32 + lane;
                Ss[row * 1024 + col] = acc[r][t * 4 + jj];
            }
    }
    __syncthreads();

    // ---- reload: warp owns full rows {warp, warp+8} ----
    float z0[32], z1[32];
    {
        const float* r0 = Ss + (size_t)warp * 1024;
        const float* r1 = Ss + (size_t)(warp + 8) * 1024;
#pragma unroll
        for (int t = 0; t < 8; t++) {
            float4 a = *(const float4*)&r0[t * 128 + lane * 4];
            float4 c = *(const float4*)&r1[t * 128 + lane * 4];
            z0[t * 4 + 0] = a.x; z0[t * 4 + 1] = a.y;
            z0[t * 4 + 2] = a.z; z0[t * 4 + 3] = a.w;
            z1[t * 4 + 0] = c.x; z1[t * 4 + 1] = c.y;
            z1[t * 4 + 2] = c.z; z1[t * 4 + 3] = c.w;
        }
    }

    // ---- sparsemax via Newton fixed point: tau <- (S-1)/k over {z>tau} ----
    float m0 = z0[0], m1 = z1[0];
#pragma unroll
    for (int i = 1; i < 32; i++) { m0 = fmaxf(m0, z0[i]); m1 = fmaxf(m1, z1[i]); }
    m0 = warp_max(m0);
    m1 = warp_max(m1);

    float t0 = m0 - 1.f, t1 = m1 - 1.f;
    for (int it = 0; it < 32; it++) {
        float S0 = 0.f, S1 = 0.f;
        int   k0 = 0,   k1 = 0;
#pragma unroll
        for (int i = 0; i < 32; i++) {
            if (z0[i] > t0) { S0 += z0[i]; k0++; }
            if (z1[i] > t1) { S1 += z1[i]; k1++; }
        }
        S0 = warp_sum(S0); S1 = warp_sum(S1);
        k0 = warp_sum_i(k0); k1 = warp_sum_i(k1);
        float n0 = __fdividef(S0 - 1.f, (float)k0);
        float n1 = __fdividef(S1 - 1.f, (float)k1);
        bool done = (n0 == t0) && (n1 == t1);   // uniform across warp
        t0 = n0; t1 = n1;
        if (done) break;
    }

    // ---- scatter nonzeros into head-mean attn ----
    const float inv12 = 1.f / 12.f;
    float* arow0 = attn + ((size_t)b * LL + qt * 16 + warp) * LL;
    float* arow1 = arow0 + (size_t)8 * LL;
#pragma unroll
    for (int i = 0; i < 32; i++) {
        int col = (i >> 2) * 128 + lane * 4 + (i & 3);
        float a = z0[i] - t0;
        if (a > 0.f) atomicAdd(&arow0[col], a * inv12);
        float c = z1[i] - t1;
        if (c > 0.f) atomicAdd(&arow1[col], c * inv12);
    }
}

// =================================================================
// Output kernel: out[b,q,:] = sum_j attn[b,q,j] * v[b,j,:]
// =================================================================
__global__ __launch_bounds__(192)
void out_kernel(const float* __restrict__ attn_arg, const float* __restrict__ v,
                float* __restrict__ out_arg)
{
    const float* attn = attn_arg ? attn_arg : g_Attn;
    float* out = out_arg ? out_arg : g_Out;

    __shared__ float srow[1024];
    __shared__ float svals[1024];
    __shared__ unsigned short sidx[1024];
    __shared__ int scnt;

    const int tid = threadIdx.x;
    const int q = blockIdx.x;
    const int b = blockIdx.y;

    const float* arow = attn + ((size_t)b * LL + q) * LL;
    for (int i = tid; i < 1024; i += 192) srow[i] = arow[i];
    __syncthreads();

    if (tid < 32) {
        int total = 0;
        for (int base = 0; base < 1024; base += 32) {
            float val = srow[base + tid];
            unsigned mask = __ballot_sync(0xffffffffu, val != 0.f);
            if (val != 0.f) {
                int pos = total + __popc(mask & ((1u << tid) - 1u));
                svals[pos] = val;
                sidx[pos] = (unsigned short)(base + tid);
            }
            total += __popc(mask);
        }
        if (tid == 0) scnt = total;
    }
    __syncthreads();

    const int cnt = scnt;
    const float4* v4 = (const float4*)(v + (size_t)b * LL * DD);
    float4 acc = make_float4(0.f, 0.f, 0.f, 0.f);

    int t = 0;
    for (; t + 4 <= cnt; t += 4) {
        float a0 = svals[t + 0], a1 = svals[t + 1];
        float a2 = svals[t + 2], a3 = svals[t + 3];
        int j0 = sidx[t + 0], j1 = sidx[t + 1];
        int j2 = sidx[t + 2], j3 = sidx[t + 3];
        float4 w0 = v4[(size_t)j0 * 192 + tid];
        float4 w1 = v4[(size_t)j1 * 192 + tid];
        float4 w2 = v4[(size_t)j2 * 192 + tid];
        float4 w3 = v4[(size_t)j3 * 192 + tid];
        acc.x += a0 * w0.x; acc.y += a0 * w0.y; acc.z += a0 * w0.z; acc.w += a0 * w0.w;
        acc.x += a1 * w1.x; acc.y += a1 * w1.y; acc.z += a1 * w1.z; acc.w += a1 * w1.w;
        acc.x += a2 * w2.x; acc.y += a2 * w2.y; acc.z += a2 * w2.z; acc.w += a2 * w2.w;
        acc.x += a3 * w3.x; acc.y += a3 * w3.y; acc.z += a3 * w3.z; acc.w += a3 * w3.w;
    }
    for (; t < cnt; t++) {
        float a = svals[t];
        int j = sidx[t];
        float4 w = v4[(size_t)j * 192 + tid];
        acc.x += a * w.x; acc.y += a * w.y; acc.z += a * w.z; acc.w += a * w.w;
    }

    float4* o4 = (float4*)(out + ((size_t)b * LL + q) * DD);
    o4[tid] = acc;
}

// =================================================================
// launch
// =================================================================
extern "C" void kernel_launch(void* const* d_in, const int* in_sizes, int n_in,
                              void* d_out, int out_size)
{
    const float* q  = (const float*)d_in[0];
    const float* k  = (const float*)d_in[1];
    const float* v  = (const float*)d_in[2];
    const float* Wq = (const float*)d_in[3];
    const float* bq = (const float*)d_in[4];
    const float* Wk = (const float*)d_in[5];
    const float* bk = (const float*)d_in[6];

    const int OUT_N = BB * LL * DD;   // 6291456
    const int ATT_N = BB * LL * LL;   // 8388608

    float* outp = (float*)d_out;
    float* out_ptr = nullptr;
    float* attn_ptr = nullptr;

    if (out_size >= OUT_N + ATT_N) {
        out_ptr = outp;
        attn_ptr = outp + OUT_N;
    } else if (out_size == ATT_N) {
        attn_ptr = outp;
    } else if (out_size >= OUT_N) {
        out_ptr = outp;
    }

    const int SMEM_BYTES = SMEM_FLOATS * 4;   // 73728
    cudaFuncSetAttribute(attn_kernel,
                         cudaFuncAttributeMaxDynamicSharedMemorySize, SMEM_BYTES);

    // 1. zero the attn accumulator (float4)
    zero_attn_kernel<<<ATT_N / 4 / 256, 256>>>(attn_ptr);

    // 2. projections
    dim3 pg(DD / 128, (BB * LL) / 128);   // (6, 64)
    proj_kernel<<<pg, 256>>>(q, Wq, bq, 0);
    proj_kernel<<<pg, 256>>>(k, Wk, bk, 1);

    // 3. scores + sparsemax + head-mean
    dim3 ag(LL / 16, NH, BB);             // (64, 12, 8)
    attn_kernel<<<ag, 256, SMEM_BYTES>>>(attn_ptr);

    // 4. sparse output gather
    dim3 og(LL, BB);                      // (1024, 8)
    out_kernel<<<og, 192>>>(attn_ptr, v, out_ptr);
}